// round 10
// baseline (speedup 1.0000x reference)
#include <cuda_runtime.h>
#include <cuda_fp16.h>
#include <mma.h>
#include <cstdint>

using namespace nvcuda;

#define N_   4
#define C_   128
#define D_   16
#define H_   64
#define W_   64
#define L_   512
#define TAPS 27
#define PD   18
#define PH   66
#define PW   66
#define LDT  72           // row pitch in halfs: 144B, LDSM conflict-free
#define NXS  18           // 2 i-chunks x 9 (kd,kh) stages
#define XW_ROWS 264       // 4 output-h input rows x 66 wpad

// ---------------------------------------------------------------------------
// Device-global scratch (allocation-free rule). .bss zero-init; g_xT pad
// borders never written -> stay zero across graph replays.
// ---------------------------------------------------------------------------
__device__ float  g_style[N_ * C_];                                    // [n][i]
__device__ __align__(16) __half g_wmod[(size_t)N_ * TAPS * C_ * C_];   // [n][t][o][i]
__device__ __align__(16) __half g_xT[(size_t)N_ * PD * PH * PW * C_];  // padded ch-last

// ---------------------------------------------------------------------------
// cp.async helpers (baseline PTX)
// ---------------------------------------------------------------------------
__device__ __forceinline__ uint32_t smem_u32(const void* p) {
    uint32_t a;
    asm("{ .reg .u64 t; cvta.to.shared.u64 t, %1; cvt.u32.u64 %0, t; }" : "=r"(a) : "l"(p));
    return a;
}
__device__ __forceinline__ void cp_async16(uint32_t dst, const void* src) {
    asm volatile("cp.async.cg.shared.global [%0], [%1], 16;" :: "r"(dst), "l"(src));
}
#define CP_COMMIT()  asm volatile("cp.async.commit_group;" ::: "memory")
#define CP_WAIT(n)   asm volatile("cp.async.wait_group %0;" :: "n"(n) : "memory")

// ---------------------------------------------------------------------------
// Kernel 1: style[n][i] = latent[n] . fc_w[i] + fc_b[i]   (warp per i)
// ---------------------------------------------------------------------------
__global__ void style_kernel(const float* __restrict__ latent,
                             const float* __restrict__ fc_w,
                             const float* __restrict__ fc_b) {
    const int n = blockIdx.y;
    const int wid = threadIdx.x >> 5, lid = threadIdx.x & 31;
    const int i = blockIdx.x * 4 + wid;
    const float* lat  = latent + n * L_;
    const float* wrow = fc_w + (size_t)i * L_;
    float acc = 0.f;
#pragma unroll 4
    for (int l = lid; l < L_; l += 32) acc = fmaf(lat[l], wrow[l], acc);
#pragma unroll
    for (int o = 16; o > 0; o >>= 1) acc += __shfl_xor_sync(0xFFFFFFFFu, acc, o);
    if (lid == 0) g_style[n * C_ + i] = acc + fc_b[i];
}

// ---------------------------------------------------------------------------
// Kernel 2: modulate + demodulate -> fp16, layout [n][t][o][i]
// ---------------------------------------------------------------------------
__global__ void modw_kernel(const float* __restrict__ weight) {
    int o = blockIdx.x, n = blockIdx.y, i = threadIdx.x;
    float s = g_style[n * C_ + i];
    const float* wp = weight + (o * C_ + i) * TAPS;
    float v[TAPS];
    float ss = 0.f;
#pragma unroll
    for (int t = 0; t < TAPS; ++t) { v[t] = wp[t] * s; ss = fmaf(v[t], v[t], ss); }
    __shared__ float red[C_];
    red[i] = ss;
    __syncthreads();
#pragma unroll
    for (int st = 64; st > 0; st >>= 1) {
        if (i < st) red[i] += red[i + st];
        __syncthreads();
    }
    float r = rsqrtf(red[0] + 1e-8f);
#pragma unroll
    for (int t = 0; t < TAPS; ++t)
        g_wmod[(((size_t)(n * TAPS + t) * C_) + o) * C_ + i] = __float2half_rn(v[t] * r);
}

// ---------------------------------------------------------------------------
// Kernel 3: transpose x -> padded channels-last fp16 xT[n][d+1][h+1][w+1][i]
// ---------------------------------------------------------------------------
__global__ __launch_bounds__(256)
void transpose_kernel(const float* __restrict__ x) {
    const int h = blockIdx.x, d = blockIdx.y, n = blockIdx.z;
    const int tid = threadIdx.x;
    __shared__ float ts[32][65];
    for (int ic = 0; ic < 4; ++ic) {
        const int i0 = ic * 32;
#pragma unroll
        for (int r = 0; r < 8; ++r) {
            int e = tid + r * 256;
            int ii = e >> 6, w = e & 63;
            ts[ii][w] = x[((((size_t)n * C_ + i0 + ii) * D_ + d) * H_ + h) * W_ + w];
        }
        __syncthreads();
        int w = tid >> 2, g = tid & 3;
        __half hb[8];
#pragma unroll
        for (int j = 0; j < 8; ++j) hb[j] = __float2half_rn(ts[g * 8 + j][w]);
        __half* dst = g_xT + ((((size_t)n * PD + d + 1) * PH + h + 1) * PW + (w + 1)) * C_ + i0 + g * 8;
        *(uint4*)dst = *(const uint4*)hb;
        __syncthreads();
    }
}

// ---------------------------------------------------------------------------
// Kernel 4: conv = 18 xs-stages x 3 kw sub-GEMMs of 128x256x64 on HMMA.
// CTA = (n, d, h-quad), 512 threads, 16 warps x (64o x 32z).
// Per xs stage: stage X window (4 h-rows x 66 wpad) + 3 kw W tiles in ONE
// cp.async group; ONE barrier; then 3 back-to-back kw sub-GEMMs reading the
// window at +kw*LDT shifts. 2-slot rings, wait-then-prefetch ordering.
// ---------------------------------------------------------------------------
__global__ __launch_bounds__(512, 1)
void conv_kernel(float* __restrict__ out) {
    const int hb = blockIdx.x, d = blockIdx.y, n = blockIdx.z;
    const int h0 = hb * 4;
    const int tid = threadIdx.x, wid = tid >> 5;

    __shared__ __align__(16) __half XW[2][XW_ROWS * LDT];    // 2 x 38016 B
    __shared__ __align__(16) __half WS[2][3][128 * LDT];     // 2 x 55296 B

    const int wo = wid >> 3;        // 0..1 -> o block of 64
    const int wz = wid & 7;         // 0..7 -> z block of 32 (z = hh*64 + w, hh 0..3)

    wmma::fragment<wmma::accumulator, 16, 16, 16, float> c[4][2];
#pragma unroll
    for (int m = 0; m < 4; ++m)
#pragma unroll
        for (int nn = 0; nn < 2; ++nn) wmma::fill_fragment(c[m][nn], 0.f);

    const __half* xT_n = g_xT + (size_t)n * PD * PH * PW * C_;
    const __half* wm_n = g_wmod + (size_t)n * TAPS * C_ * C_;

    // X window: xs = ic*9 + kd*3 + kh. 2112 16B chunks (264 rows x 8).
    auto stageX = [&](int xs, int slot) {
        const int ic = xs / 9, rr = xs - ic * 9;
        const int kd = rr / 3, kh = rr - kd * 3;
        const __half* base = xT_n + (((size_t)(d + kd) * PH) + (h0 + kh)) * PW * C_ + ic * 64;
        const uint32_t dst = smem_u32(&XW[slot][0]);
#pragma unroll
        for (int it = 0; it < 4; ++it) {
            int cch = tid + it * 512;                 // 0..2047
            int row = cch >> 3, q = cch & 7;          // row = hh*66+ww, 0..255
            int hh = row / 66, ww = row - hh * 66;
            cp_async16(dst + (uint32_t)(row * LDT + q * 8) * 2,
                       base + ((size_t)hh * PW + ww) * C_ + q * 8);
        }
        if (tid < 64) {                               // chunks 2048..2111 (rows 256..263, hh=3)
            int cch = 2048 + tid;
            int row = cch >> 3, q = cch & 7;
            int ww = row - 198;
            cp_async16(dst + (uint32_t)(row * LDT + q * 8) * 2,
                       base + ((size_t)3 * PW + ww) * C_ + q * 8);
        }
    };

    // W tiles for all 3 kw of stage xs: 3072 chunks.
    auto stageW3 = [&](int xs, int slot) {
        const int ic = xs / 9, rr = xs - ic * 9;
        const __half* wb = wm_n + (size_t)(rr * 3) * C_ * C_ + ic * 64;   // tap rr*3 + kw
        const uint32_t dst = smem_u32(&WS[slot][0][0]);
#pragma unroll
        for (int it = 0; it < 6; ++it) {
            int cch = tid + it * 512;                 // 0..3071
            int kw = cch >> 10, rem = cch & 1023;
            int row = rem >> 3, q = rem & 7;
            cp_async16(dst + (uint32_t)((kw * 128 + row) * LDT + q * 8) * 2,
                       wb + (size_t)kw * C_ * C_ + (size_t)row * C_ + q * 8);
        }
    };

    auto compute = [&](int kw, int slot) {
        const __half* Wbase = &WS[slot][kw][wo * 64 * LDT];
        const int z0 = wz * 32;
        const int hh0 = z0 >> 6, w00 = z0 & 63;
        const int z1 = z0 + 16;
        const int hh1 = z1 >> 6, w01 = z1 & 63;
        const __half* Xb0 = &XW[slot][(hh0 * 66 + w00 + kw) * LDT];
        const __half* Xb1 = &XW[slot][(hh1 * 66 + w01 + kw) * LDT];
#pragma unroll
        for (int k = 0; k < 4; ++k) {
            wmma::fragment<wmma::matrix_a, 16, 16, 16, __half, wmma::row_major> a[4];
            wmma::fragment<wmma::matrix_b, 16, 16, 16, __half, wmma::col_major> b[2];
            wmma::load_matrix_sync(b[0], Xb0 + k * 16, LDT);
            wmma::load_matrix_sync(b[1], Xb1 + k * 16, LDT);
#pragma unroll
            for (int m = 0; m < 4; ++m) {
                wmma::load_matrix_sync(a[m], Wbase + (m * 16) * LDT + k * 16, LDT);
#pragma unroll
                for (int nn = 0; nn < 2; ++nn)
                    wmma::mma_sync(c[m][nn], a[m], b[nn], c[m][nn]);
            }
        }
    };

    // Wait-then-prefetch: slot (s+1)&1 is proven drained by the barrier
    // (compute of stage s-1 finished before it), so 2-slot rings are safe.
    stageX(0, 0); stageW3(0, 0); CP_COMMIT();
    for (int s = 0; s < NXS; ++s) {
        CP_WAIT(0);                      // group s complete (only one pending)
        __syncthreads();                 // visible everywhere; stage s-1 compute done
        if (s + 1 < NXS) {
            stageX(s + 1, (s + 1) & 1);
            stageW3(s + 1, (s + 1) & 1);
            CP_COMMIT();
        }
        compute(0, s & 1);
        compute(1, s & 1);
        compute(2, s & 1);
    }

    // Epilogue: 16x16 fragments straight to gmem (z tiles never straddle hh).
#pragma unroll
    for (int m = 0; m < 4; ++m) {
        const int o = wo * 64 + m * 16;
#pragma unroll
        for (int nn = 0; nn < 2; ++nn) {
            const int z = wz * 32 + nn * 16;
            const int hh = z >> 6, w0 = z & 63;
            float* dst = out + (((size_t)n * C_ + o) * D_ + d) * (H_ * W_) + (h0 + hh) * W_ + w0;
            wmma::store_matrix_sync(dst, c[m][nn], D_ * H_ * W_, wmma::mem_row_major);
        }
    }
}

// ---------------------------------------------------------------------------
extern "C" void kernel_launch(void* const* d_in, const int* in_sizes, int n_in,
                              void* d_out, int out_size) {
    const float* x      = (const float*)d_in[0];
    const float* latent = (const float*)d_in[1];
    const float* weight = (const float*)d_in[2];
    const float* fc_w   = (const float*)d_in[3];
    const float* fc_b   = (const float*)d_in[4];
    float* out = (float*)d_out;

    style_kernel<<<dim3(C_ / 4, N_), 128>>>(latent, fc_w, fc_b);
    modw_kernel<<<dim3(C_, N_), C_>>>(weight);
    transpose_kernel<<<dim3(H_, D_, N_), 256>>>(x);
    conv_kernel<<<dim3(H_ / 4, D_, N_), 512>>>(out);
}